// round 5
// baseline (speedup 1.0000x reference)
#include <cuda_runtime.h>
#include <cstddef>

#define NUM_USERS 200000
#define NUM_ITEMS 100000
#define N_NODES   (NUM_USERS + NUM_ITEMS)
#define DIM       64
#define NNZ       4000000

// Scratch ping-pong buffers (allocation in kernel_launch is forbidden).
__device__ float g_bufA[(size_t)N_NODES * DIM];
__device__ float g_bufB[(size_t)N_NODES * DIM];

// ---------------------------------------------------------------------------
// init: cur = concat(user_emb, item_emb); out = 0.25 * cur (layer-0 term);
//       nxt = 0 (scatter target for layer 1)
// ---------------------------------------------------------------------------
__global__ void init_kernel(const float* __restrict__ ue,
                            const float* __restrict__ ie,
                            float* __restrict__ cur,
                            float* __restrict__ nxt,
                            float* __restrict__ out) {
    size_t i = (size_t)blockIdx.x * blockDim.x + threadIdx.x;   // float4 index
    const size_t total = (size_t)N_NODES * DIM / 4;
    if (i >= total) return;
    const size_t uf4 = (size_t)NUM_USERS * DIM / 4;
    float4 v;
    if (i < uf4) v = ((const float4*)ue)[i];
    else         v = ((const float4*)ie)[i - uf4];
    ((float4*)cur)[i] = v;
    ((float4*)out)[i] = make_float4(0.25f * v.x, 0.25f * v.y,
                                    0.25f * v.z, 0.25f * v.w);
    ((float4*)nxt)[i] = make_float4(0.f, 0.f, 0.f, 0.f);
}

// ---------------------------------------------------------------------------
// spmm: y[rows[e]] += vals[e] * x[cols[e]]   (16 threads per edge, float4 each)
// ---------------------------------------------------------------------------
__global__ void __launch_bounds__(256)
spmm_kernel(const float* __restrict__ vals,
            const int*   __restrict__ rows,
            const int*   __restrict__ cols,
            const float* __restrict__ x,
            float*       __restrict__ y) {
    size_t t = (size_t)blockIdx.x * blockDim.x + threadIdx.x;
    size_t e = t >> 4;          // edge index
    int    d = (int)(t & 15);   // float4 slot within the 64-float row
    if (e >= NNZ) return;
    int   r = __ldg(rows + e);
    int   c = __ldg(cols + e);
    float v = __ldg(vals + e);
    float4 xv = __ldg(((const float4*)(x + (size_t)c * DIM)) + d);
    float4 m  = make_float4(v * xv.x, v * xv.y, v * xv.z, v * xv.w);
    atomicAdd(((float4*)(y + (size_t)r * DIM)) + d, m);
}

// ---------------------------------------------------------------------------
// accum: out += 0.25 * next; also zero `dead` (scatter target for next layer)
// ---------------------------------------------------------------------------
__global__ void accum_kernel(const float* __restrict__ next,
                             float* __restrict__ out,
                             float* __restrict__ dead,
                             int    do_zero) {
    size_t i = (size_t)blockIdx.x * blockDim.x + threadIdx.x;
    if (i >= (size_t)N_NODES * DIM / 4) return;
    float4 n = ((const float4*)next)[i];
    float4 o = ((float4*)out)[i];
    o.x += 0.25f * n.x;
    o.y += 0.25f * n.y;
    o.z += 0.25f * n.z;
    o.w += 0.25f * n.w;
    ((float4*)out)[i] = o;
    if (do_zero)
        ((float4*)dead)[i] = make_float4(0.f, 0.f, 0.f, 0.f);
}

// ---------------------------------------------------------------------------
// launch
// ---------------------------------------------------------------------------
extern "C" void kernel_launch(void* const* d_in, const int* in_sizes, int n_in,
                              void* d_out, int out_size) {
    const float* ue   = (const float*)d_in[0];
    const float* ie   = (const float*)d_in[1];
    const float* vals = (const float*)d_in[2];
    const int*   rows = (const int*)d_in[3];
    const int*   cols = (const int*)d_in[4];
    float* out = (float*)d_out;

    float* bufA = nullptr;
    float* bufB = nullptr;
    cudaGetSymbolAddress((void**)&bufA, g_bufA);
    cudaGetSymbolAddress((void**)&bufB, g_bufB);

    const int TPB = 256;
    const size_t nf4 = (size_t)N_NODES * DIM / 4;           // 4.8M float4s
    const int grid_f4 = (int)((nf4 + TPB - 1) / TPB);
    const size_t spmm_threads = (size_t)NNZ * 16;           // 64M threads
    const int grid_spmm = (int)((spmm_threads + TPB - 1) / TPB);

    // cur = concat embeddings, out = 0.25*cur, nxt zeroed for first scatter
    init_kernel<<<grid_f4, TPB>>>(ue, ie, bufA, bufB, out);

    float* cur = bufA;
    float* nxt = bufB;
    for (int layer = 0; layer < 3; ++layer) {
        spmm_kernel<<<grid_spmm, TPB>>>(vals, rows, cols, cur, nxt);
        // out += 0.25*nxt; zero `cur` so it can be the scatter target next layer
        accum_kernel<<<grid_f4, TPB>>>(nxt, out, cur, layer < 2 ? 1 : 0);
        float* tmp = cur; cur = nxt; nxt = tmp;
    }
}